// round 11
// baseline (speedup 1.0000x reference)
#include <cuda_runtime.h>
#include <cstdint>

#define DIM 64
#define MAX_NODES 100000
#define MAX_GRAPHS 1000

// ---------------- scratch (device globals; no allocations allowed) ----------
__device__ float g_agg[(size_t)MAX_NODES * DIM];   // 25.6 MB, reused across convs
__device__ float g_h1[(size_t)MAX_NODES * DIM];    // conv1 output
__device__ float g_sums[MAX_GRAPHS * DIM];         // pooled sums
__device__ float g_cnt[MAX_GRAPHS];                // node counts per graph

// ---------------- zeroing --------------------------------------------------
__global__ void zero_kernel(int full) {
    size_t i = (size_t)blockIdx.x * blockDim.x + threadIdx.x;
    const size_t total4 = (size_t)MAX_NODES * DIM / 4;
    float4 z = make_float4(0.f, 0.f, 0.f, 0.f);
    float4* a4 = reinterpret_cast<float4*>(g_agg);
    for (size_t j = i; j < total4; j += (size_t)gridDim.x * blockDim.x) a4[j] = z;
    if (full) {
        if (i < (size_t)MAX_GRAPHS * DIM / 4) reinterpret_cast<float4*>(g_sums)[i] = z;
        if (i < MAX_GRAPHS) g_cnt[i] = 0.f;
    }
}

// ---------------- edge scatter: agg[dst] += relu(X[src] + ea*We + be) ------
// 16 threads per edge, float4 per thread, vector RED atomics.
// Indices are int32 (JAX x64 disabled downcasts the reference's int64).
__global__ void edge_scatter(int useH1,
                             const float* __restrict__ Xext,
                             const int* __restrict__ ei,
                             const float* __restrict__ ea,
                             const float* __restrict__ We,
                             const float* __restrict__ be,
                             int E) {
    const float* X = useH1 ? g_h1 : Xext;
    int t = blockIdx.x * blockDim.x + threadIdx.x;
    int e = t >> 4;
    if (e >= E) return;
    int c = (t & 15) * 4;

    int s = ei[e];
    int d = ei[(size_t)E + e];
    float a = ea[e];

    float4 xv = *reinterpret_cast<const float4*>(X + (size_t)s * DIM + c);
    float4 w  = *reinterpret_cast<const float4*>(We + c);
    float4 b  = *reinterpret_cast<const float4*>(be + c);

    float m0 = fmaxf(xv.x + fmaf(a, w.x, b.x), 0.f);
    float m1 = fmaxf(xv.y + fmaf(a, w.y, b.y), 0.f);
    float m2 = fmaxf(xv.z + fmaf(a, w.z, b.z), 0.f);
    float m3 = fmaxf(xv.w + fmaf(a, w.w, b.w), 0.f);

    float* dst = g_agg + (size_t)d * DIM + c;
    asm volatile("red.global.add.v4.f32 [%0], {%1,%2,%3,%4};"
                 :: "l"(dst), "f"(m0), "f"(m1), "f"(m2), "f"(m3) : "memory");
}

// ---------------- fused node MLP -------------------------------------------
// h = relu( relu((X + agg) @ Wa + ba) @ Wb + bb )
// mode 0: X = Xext, store result to g_h1
// mode 1: X = g_h1, fuse mean-pool atomics (no store of h2)
extern __shared__ float sm_mlp[];
__global__ __launch_bounds__(128) void node_mlp(
    int mode,
    const float* __restrict__ Xext,
    const float* __restrict__ Wa, const float* __restrict__ ba,
    const float* __restrict__ Wb, const float* __restrict__ bb,
    const int* __restrict__ batch,
    int n)
{
    float* Ws0  = sm_mlp;                 // 4096 floats
    float* Ws1  = sm_mlp + 4096;          // 4096 floats
    float* bs   = sm_mlp + 8192;          // 128 floats
    float* tile = sm_mlp + 8320;          // 128 * 65 floats

    const float* X = mode ? g_h1 : Xext;
    int tid  = threadIdx.x;
    int base = blockIdx.x * 128;
    int node = base + tid;

    for (int i = tid; i < 4096; i += 128) { Ws0[i] = Wa[i]; Ws1[i] = Wb[i]; }
    if (tid < 64) { bs[tid] = ba[tid]; bs[64 + tid] = bb[tid]; }

    for (int i = tid; i < 128 * DIM; i += 128) {
        int r = i >> 6, c = i & 63;
        int nd = base + r;
        float v = 0.f;
        if (nd < n) {
            size_t off = (size_t)nd * DIM + c;
            v = X[off] + g_agg[off];
        }
        tile[r * 65 + c] = v;
    }
    __syncthreads();

    float acc[64];

    // ---- linear 1 + ReLU ----
    #pragma unroll
    for (int j = 0; j < 64; j++) acc[j] = bs[j];
    #pragma unroll 4
    for (int k = 0; k < 64; k++) {
        float tk = tile[tid * 65 + k];
        const float4* wrow = reinterpret_cast<const float4*>(Ws0 + k * 64);
        #pragma unroll
        for (int j = 0; j < 16; j++) {
            float4 w = wrow[j];
            acc[4*j+0] = fmaf(tk, w.x, acc[4*j+0]);
            acc[4*j+1] = fmaf(tk, w.y, acc[4*j+1]);
            acc[4*j+2] = fmaf(tk, w.z, acc[4*j+2]);
            acc[4*j+3] = fmaf(tk, w.w, acc[4*j+3]);
        }
    }
    // write u (relu) back into own row; no sync needed (thread-private row)
    #pragma unroll
    for (int j = 0; j < 64; j++) tile[tid * 65 + j] = fmaxf(acc[j], 0.f);

    // ---- linear 2 ----
    #pragma unroll
    for (int j = 0; j < 64; j++) acc[j] = bs[64 + j];
    #pragma unroll 4
    for (int k = 0; k < 64; k++) {
        float tk = tile[tid * 65 + k];
        const float4* wrow = reinterpret_cast<const float4*>(Ws1 + k * 64);
        #pragma unroll
        for (int j = 0; j < 16; j++) {
            float4 w = wrow[j];
            acc[4*j+0] = fmaf(tk, w.x, acc[4*j+0]);
            acc[4*j+1] = fmaf(tk, w.y, acc[4*j+1]);
            acc[4*j+2] = fmaf(tk, w.z, acc[4*j+2]);
            acc[4*j+3] = fmaf(tk, w.w, acc[4*j+3]);
        }
    }
    // outer ReLU (post-conv relu in the reference)
    #pragma unroll
    for (int j = 0; j < 64; j++) acc[j] = fmaxf(acc[j], 0.f);

    if (mode == 0) {
        // stage through smem for coalesced stores to g_h1
        #pragma unroll
        for (int j = 0; j < 64; j++) tile[tid * 65 + j] = acc[j];
        __syncthreads();
        for (int i = tid; i < 128 * DIM; i += 128) {
            int r = i >> 6, c = i & 63;
            int nd = base + r;
            if (nd < n) g_h1[(size_t)nd * DIM + c] = tile[r * 65 + c];
        }
    } else {
        if (node < n) {
            int g = batch[node];
            float* s = g_sums + (size_t)g * DIM;
            #pragma unroll
            for (int j = 0; j < 64; j += 4)
                asm volatile("red.global.add.v4.f32 [%0], {%1,%2,%3,%4};"
                             :: "l"(s + j), "f"(acc[j]), "f"(acc[j+1]),
                                "f"(acc[j+2]), "f"(acc[j+3]) : "memory");
            atomicAdd(&g_cnt[g], 1.0f);
        }
    }
}

// ---------------- classifier over graphs -----------------------------------
__global__ void classifier(const float* __restrict__ Wc1, const float* __restrict__ bc1,
                           const float* __restrict__ Wc2, const float* __restrict__ bc2,
                           float* __restrict__ out, int G)
{
    int g = blockIdx.x * blockDim.x + threadIdx.x;
    if (g >= G) return;
    float inv = 1.0f / fmaxf(g_cnt[g], 1.0f);
    float p[64];
    #pragma unroll
    for (int k = 0; k < 64; k++) p[k] = g_sums[g * 64 + k] * inv;
    float o = bc2[0];
    for (int j = 0; j < 64; j++) {
        float u = bc1[j];
        #pragma unroll
        for (int k = 0; k < 64; k++) u = fmaf(p[k], Wc1[k * 64 + j], u);
        o = fmaf(fmaxf(u, 0.f), Wc2[j], o);
    }
    out[g] = o;
}

// ---------------- launch ----------------------------------------------------
extern "C" void kernel_launch(void* const* d_in, const int* in_sizes, int n_in,
                              void* d_out, int out_size) {
    const float* x     = (const float*)d_in[0];
    const int*   ei    = (const int*)d_in[1];
    const float* eattr = (const float*)d_in[2];
    const int*   batch = (const int*)d_in[3];
    const float *W1a = (const float*)d_in[4],  *b1a = (const float*)d_in[5];
    const float *W1b = (const float*)d_in[6],  *b1b = (const float*)d_in[7];
    const float *We1 = (const float*)d_in[8],  *be1 = (const float*)d_in[9];
    const float *W2a = (const float*)d_in[10], *b2a = (const float*)d_in[11];
    const float *W2b = (const float*)d_in[12], *b2b = (const float*)d_in[13];
    const float *We2 = (const float*)d_in[14], *be2 = (const float*)d_in[15];
    const float *Wc1 = (const float*)d_in[16], *bc1 = (const float*)d_in[17];
    const float *Wc2 = (const float*)d_in[18], *bc2 = (const float*)d_in[19];
    float* out = (float*)d_out;

    int N = in_sizes[0] / DIM;
    int E = in_sizes[2];           // edge_attr has EDGE_DIM=1 -> count == E
    int G = out_size;              // [G, 1]

    const int SMEM = (4096 * 2 + 128 + 128 * 65) * (int)sizeof(float);  // ~66.5 KB
    cudaFuncSetAttribute(node_mlp, cudaFuncAttributeMaxDynamicSharedMemorySize, SMEM);

    int edge_blocks = (E * 16 + 255) / 256;
    int node_blocks = (N + 127) / 128;

    // conv1
    zero_kernel<<<2048, 256>>>(1);
    edge_scatter<<<edge_blocks, 256>>>(0, x, ei, eattr, We1, be1, E);
    node_mlp<<<node_blocks, 128, SMEM>>>(0, x, W1a, b1a, W1b, b1b, batch, N);
    // conv2 (+ fused mean-pool sums)
    zero_kernel<<<2048, 256>>>(0);
    edge_scatter<<<edge_blocks, 256>>>(1, x, ei, eattr, We2, be2, E);
    node_mlp<<<node_blocks, 128, SMEM>>>(1, x, W2a, b2a, W2b, b2b, batch, N);
    // classifier
    classifier<<<(G + 127) / 128, 128>>>(Wc1, bc1, Wc2, bc2, out, G);
}

// round 12
// speedup vs baseline: 1.4774x; 1.4774x over previous
#include <cuda_runtime.h>
#include <cstdint>

#define DIM 64
#define MAX_NODES 100000
#define MAX_GRAPHS 1000

// ---------------- scratch (device globals; no allocations allowed) ----------
__device__ float g_agg[(size_t)MAX_NODES * DIM];   // 25.6 MB, reused across convs
__device__ float g_h1[(size_t)MAX_NODES * DIM];    // conv1 output
__device__ float g_sums[MAX_GRAPHS * DIM];         // pooled sums
__device__ float g_cnt[MAX_GRAPHS];                // node counts per graph

// ---------------- zeroing --------------------------------------------------
__global__ void zero_kernel(int full) {
    size_t i = (size_t)blockIdx.x * blockDim.x + threadIdx.x;
    const size_t total4 = (size_t)MAX_NODES * DIM / 4;
    float4 z = make_float4(0.f, 0.f, 0.f, 0.f);
    float4* a4 = reinterpret_cast<float4*>(g_agg);
    for (size_t j = i; j < total4; j += (size_t)gridDim.x * blockDim.x) a4[j] = z;
    if (full) {
        if (i < (size_t)MAX_GRAPHS * DIM / 4) reinterpret_cast<float4*>(g_sums)[i] = z;
        if (i < MAX_GRAPHS) g_cnt[i] = 0.f;
    }
}

// ---------------- edge scatter: agg[dst] += relu(X[src] + ea*We + be) ------
// 16 threads per edge, float4 per thread, vector RED atomics.
// Indices are int32 (JAX x64 disabled downcasts the reference's int64).
__global__ void edge_scatter(int useH1,
                             const float* __restrict__ Xext,
                             const int* __restrict__ ei,
                             const float* __restrict__ ea,
                             const float* __restrict__ We,
                             const float* __restrict__ be,
                             int E) {
    const float* X = useH1 ? g_h1 : Xext;
    int t = blockIdx.x * blockDim.x + threadIdx.x;
    int e = t >> 4;
    if (e >= E) return;
    int c = (t & 15) * 4;

    int s = ei[e];
    int d = ei[(size_t)E + e];
    float a = ea[e];

    float4 xv = *reinterpret_cast<const float4*>(X + (size_t)s * DIM + c);
    float4 w  = *reinterpret_cast<const float4*>(We + c);
    float4 b  = *reinterpret_cast<const float4*>(be + c);

    float m0 = fmaxf(xv.x + fmaf(a, w.x, b.x), 0.f);
    float m1 = fmaxf(xv.y + fmaf(a, w.y, b.y), 0.f);
    float m2 = fmaxf(xv.z + fmaf(a, w.z, b.z), 0.f);
    float m3 = fmaxf(xv.w + fmaf(a, w.w, b.w), 0.f);

    float* dst = g_agg + (size_t)d * DIM + c;
    asm volatile("red.global.add.v4.f32 [%0], {%1,%2,%3,%4};"
                 :: "l"(dst), "f"(m0), "f"(m1), "f"(m2), "f"(m3) : "memory");
}

// ---------------- fused node MLP -------------------------------------------
// h = relu( relu((X + agg) @ Wa + ba) @ Wb + bb )
// mode 0: X = Xext, store result to g_h1
// mode 1: X = g_h1, fuse mean-pool atomics (no store of h2)
extern __shared__ float sm_mlp[];
__global__ __launch_bounds__(128) void node_mlp(
    int mode,
    const float* __restrict__ Xext,
    const float* __restrict__ Wa, const float* __restrict__ ba,
    const float* __restrict__ Wb, const float* __restrict__ bb,
    const int* __restrict__ batch,
    int n)
{
    float* Ws0  = sm_mlp;                 // 4096 floats
    float* Ws1  = sm_mlp + 4096;          // 4096 floats
    float* bs   = sm_mlp + 8192;          // 128 floats
    float* tile = sm_mlp + 8320;          // 128 * 65 floats

    const float* X = mode ? g_h1 : Xext;
    int tid  = threadIdx.x;
    int base = blockIdx.x * 128;
    int node = base + tid;

    for (int i = tid; i < 4096; i += 128) { Ws0[i] = Wa[i]; Ws1[i] = Wb[i]; }
    if (tid < 64) { bs[tid] = ba[tid]; bs[64 + tid] = bb[tid]; }

    for (int i = tid; i < 128 * DIM; i += 128) {
        int r = i >> 6, c = i & 63;
        int nd = base + r;
        float v = 0.f;
        if (nd < n) {
            size_t off = (size_t)nd * DIM + c;
            v = X[off] + g_agg[off];
        }
        tile[r * 65 + c] = v;
    }
    __syncthreads();

    float acc[64];

    // ---- linear 1 + ReLU ----
    #pragma unroll
    for (int j = 0; j < 64; j++) acc[j] = bs[j];
    #pragma unroll 4
    for (int k = 0; k < 64; k++) {
        float tk = tile[tid * 65 + k];
        const float4* wrow = reinterpret_cast<const float4*>(Ws0 + k * 64);
        #pragma unroll
        for (int j = 0; j < 16; j++) {
            float4 w = wrow[j];
            acc[4*j+0] = fmaf(tk, w.x, acc[4*j+0]);
            acc[4*j+1] = fmaf(tk, w.y, acc[4*j+1]);
            acc[4*j+2] = fmaf(tk, w.z, acc[4*j+2]);
            acc[4*j+3] = fmaf(tk, w.w, acc[4*j+3]);
        }
    }
    // write u (relu) back into own row; no sync needed (thread-private row)
    #pragma unroll
    for (int j = 0; j < 64; j++) tile[tid * 65 + j] = fmaxf(acc[j], 0.f);

    // ---- linear 2 ----
    #pragma unroll
    for (int j = 0; j < 64; j++) acc[j] = bs[64 + j];
    #pragma unroll 4
    for (int k = 0; k < 64; k++) {
        float tk = tile[tid * 65 + k];
        const float4* wrow = reinterpret_cast<const float4*>(Ws1 + k * 64);
        #pragma unroll
        for (int j = 0; j < 16; j++) {
            float4 w = wrow[j];
            acc[4*j+0] = fmaf(tk, w.x, acc[4*j+0]);
            acc[4*j+1] = fmaf(tk, w.y, acc[4*j+1]);
            acc[4*j+2] = fmaf(tk, w.z, acc[4*j+2]);
            acc[4*j+3] = fmaf(tk, w.w, acc[4*j+3]);
        }
    }
    // outer ReLU (post-conv relu in the reference)
    #pragma unroll
    for (int j = 0; j < 64; j++) acc[j] = fmaxf(acc[j], 0.f);

    if (mode == 0) {
        // stage through smem for coalesced stores to g_h1
        #pragma unroll
        for (int j = 0; j < 64; j++) tile[tid * 65 + j] = acc[j];
        __syncthreads();
        for (int i = tid; i < 128 * DIM; i += 128) {
            int r = i >> 6, c = i & 63;
            int nd = base + r;
            if (nd < n) g_h1[(size_t)nd * DIM + c] = tile[r * 65 + c];
        }
    } else {
        if (node < n) {
            int g = batch[node];
            float* s = g_sums + (size_t)g * DIM;
            #pragma unroll
            for (int j = 0; j < 64; j += 4)
                asm volatile("red.global.add.v4.f32 [%0], {%1,%2,%3,%4};"
                             :: "l"(s + j), "f"(acc[j]), "f"(acc[j+1]),
                                "f"(acc[j+2]), "f"(acc[j+3]) : "memory");
            atomicAdd(&g_cnt[g], 1.0f);
        }
    }
}

// ---------------- classifier over graphs -----------------------------------
__global__ void classifier(const float* __restrict__ Wc1, const float* __restrict__ bc1,
                           const float* __restrict__ Wc2, const float* __restrict__ bc2,
                           float* __restrict__ out, int G)
{
    int g = blockIdx.x * blockDim.x + threadIdx.x;
    if (g >= G) return;
    float inv = 1.0f / fmaxf(g_cnt[g], 1.0f);
    float p[64];
    #pragma unroll
    for (int k = 0; k < 64; k++) p[k] = g_sums[g * 64 + k] * inv;
    float o = bc2[0];
    for (int j = 0; j < 64; j++) {
        float u = bc1[j];
        #pragma unroll
        for (int k = 0; k < 64; k++) u = fmaf(p[k], Wc1[k * 64 + j], u);
        o = fmaf(fmaxf(u, 0.f), Wc2[j], o);
    }
    out[g] = o;
}

// ---------------- launch ----------------------------------------------------
extern "C" void kernel_launch(void* const* d_in, const int* in_sizes, int n_in,
                              void* d_out, int out_size) {
    const float* x     = (const float*)d_in[0];
    const int*   ei    = (const int*)d_in[1];
    const float* eattr = (const float*)d_in[2];
    const int*   batch = (const int*)d_in[3];
    const float *W1a = (const float*)d_in[4],  *b1a = (const float*)d_in[5];
    const float *W1b = (const float*)d_in[6],  *b1b = (const float*)d_in[7];
    const float *We1 = (const float*)d_in[8],  *be1 = (const float*)d_in[9];
    const float *W2a = (const float*)d_in[10], *b2a = (const float*)d_in[11];
    const float *W2b = (const float*)d_in[12], *b2b = (const float*)d_in[13];
    const float *We2 = (const float*)d_in[14], *be2 = (const float*)d_in[15];
    const float *Wc1 = (const float*)d_in[16], *bc1 = (const float*)d_in[17];
    const float *Wc2 = (const float*)d_in[18], *bc2 = (const float*)d_in[19];
    float* out = (float*)d_out;

    int N = in_sizes[0] / DIM;
    int E = in_sizes[2];           // edge_attr has EDGE_DIM=1 -> count == E
    int G = out_size;              // [G, 1]

    const int SMEM = (4096 * 2 + 128 + 128 * 65) * (int)sizeof(float);  // ~66.5 KB
    cudaFuncSetAttribute(node_mlp, cudaFuncAttributeMaxDynamicSharedMemorySize, SMEM);

    int edge_blocks = (E * 16 + 255) / 256;
    int node_blocks = (N + 127) / 128;

    // conv1
    zero_kernel<<<2048, 256>>>(1);
    edge_scatter<<<edge_blocks, 256>>>(0, x, ei, eattr, We1, be1, E);
    node_mlp<<<node_blocks, 128, SMEM>>>(0, x, W1a, b1a, W1b, b1b, batch, N);
    // conv2 (+ fused mean-pool sums)
    zero_kernel<<<2048, 256>>>(0);
    edge_scatter<<<edge_blocks, 256>>>(1, x, ei, eattr, We2, be2, E);
    node_mlp<<<node_blocks, 128, SMEM>>>(1, x, W2a, b2a, W2b, b2b, batch, N);
    // classifier
    classifier<<<(G + 127) / 128, 128>>>(Wc1, bc1, Wc2, bc2, out, G);
}